// round 16
// baseline (speedup 1.0000x reference)
#include <cuda_runtime.h>

#define TPB 128
#define PTS_PER_BLK (2 * TPB)

// one packed (c,c) u64 per coupling constant: [0,45) = C2, [45,234) = C3
// NOTE: must be read as SCALAR u64 (LDCU path); 128-bit reads fall to LDC (8-cyc floor).
__constant__ unsigned long long cPack[234];

// ---------- packed f32x2 helpers ----------
typedef unsigned long long pf;

__device__ __forceinline__ pf f2fma(pf a, pf b, pf c) {
    pf d; asm("fma.rn.f32x2 %0, %1, %2, %3;" : "=l"(d) : "l"(a), "l"(b), "l"(c)); return d;
}
__device__ __forceinline__ pf f2mul(pf a, pf b) {
    pf d; asm("mul.rn.f32x2 %0, %1, %2;" : "=l"(d) : "l"(a), "l"(b)); return d;
}
__device__ __forceinline__ pf f2add(pf a, pf b) {
    pf d; asm("add.rn.f32x2 %0, %1, %2;" : "=l"(d) : "l"(a), "l"(b)); return d;
}
__device__ __forceinline__ pf f2pack(float lo, float hi) {
    pf d; asm("mov.b64 %0, {%1, %2};" : "=l"(d) : "f"(lo), "f"(hi)); return d;
}
__device__ __forceinline__ void f2unpack(pf p, float& lo, float& hi) {
    asm("mov.b64 {%0, %1}, %2;" : "=f"(lo), "=f"(hi) : "l"(p));
}

__global__ void prep_kernel(const float* __restrict__ C2, const float* __restrict__ C3,
                            unsigned long long* __restrict__ dst) {
    int i = threadIdx.x;
    if (i < 234) {
        float c = (i < 45) ? C2[i] : C3[i - 45];
        unsigned int b = __float_as_uint(c);
        dst[i] = ((unsigned long long)b << 32) | b;
    }
}

__global__ __launch_bounds__(TPB, 6)
void hop_invariant_kernel(const float* __restrict__ tf,
                          float* __restrict__ out,
                          int N)
{
    __shared__ __align__(16) float sO[PTS_PER_BLK * 13];

    const unsigned long long* cp = cPack;
#define C2P(i) cp[i]
#define C3P(i) cp[45 + (i)]

    const int tid = threadIdx.x;
    const int blk_start = blockIdx.x * PTS_PER_BLK;
    const int nA = blk_start + tid;
    const int nB = nA + TPB;

    if (nA < N) {
        // ---- load 16 features for both points, unconditional & front-batched:
        // clamp B's index to a valid point so all 8 LDG.128 issue back-to-back
        // (no BSSY/BSYNC, MLP_p1 = 8). Garbage hi-lanes in the tail block are
        // never written out (writeback is bounded by `valid`).
        const int nBc = (nB < N) ? nB : (N - 1);
        const float4* pA = reinterpret_cast<const float4*>(tf + (size_t)nA * 16);
        const float4* pB = reinterpret_cast<const float4*>(tf + (size_t)nBc * 16);
        float4 a0 = pA[0], a1 = pA[1], a2 = pA[2], a3 = pA[3];
        float4 b0 = pB[0], b1 = pB[1], b2 = pB[2], b3 = pB[3];

        // ---- pack lanes: lo = point A, hi = point B ----
        const pf s  = f2pack(a0.x, b0.x);
        pf v[3] = { f2pack(a0.y, b0.y), f2pack(a0.z, b0.z), f2pack(a0.w, b0.w) };
        pf q[5] = { f2pack(a1.x, b1.x), f2pack(a1.y, b1.y),
                    f2pack(a1.z, b1.z), f2pack(a1.w, b1.w), f2pack(a2.x, b2.x) };
        pf t[7] = { f2pack(a2.y, b2.y), f2pack(a2.z, b2.z), f2pack(a2.w, b2.w),
                    f2pack(a3.x, b3.x), f2pack(a3.y, b3.y), f2pack(a3.z, b3.z),
                    f2pack(a3.w, b3.w) };

        // PDL: wait for prep_kernel's cPack writes before first constant read.
        cudaGridDependencySynchronize();

        // ---- ah[r] = sum_m C2[r][m] * q[m]  (scalar u64 LDCU) ----
        pf ah[9];
        #pragma unroll
        for (int r = 0; r < 9; r++) {
            pf acc = f2mul(C2P(r * 5 + 0), q[0]);
            acc = f2fma(C2P(r * 5 + 1), q[1], acc);
            acc = f2fma(C2P(r * 5 + 2), q[2], acc);
            acc = f2fma(C2P(r * 5 + 3), q[3], acc);
            acc = f2fma(C2P(r * 5 + 4), q[4], acc);
            ah[r] = acc;
        }

        // ---- stream bh 3-at-a-time over (i,j); accumulate b (sym), e, I8 ----
        pf b00 = 0, b01 = 0, b02 = 0, b11 = 0, b12 = 0, b22 = 0;
        pf e0 = 0, e1 = 0, e2 = 0;
        pf I8 = 0;

        #pragma unroll
        for (int i = 0; i < 3; i++) {
            pf i8i = 0;
            #pragma unroll
            for (int j = 0; j < 3; j++) {
                pf bj0, bj1, bj2;
                {
                    const int base = (i * 9 + j * 3) * 7;
                    pf x0 = f2mul(C3P(base + 0), t[0]);
                    pf x1 = f2mul(C3P(base + 7), t[0]);
                    pf x2 = f2mul(C3P(base + 14), t[0]);
                    #pragma unroll
                    for (int m = 1; m < 7; m++) {
                        x0 = f2fma(C3P(base + m),      t[m], x0);
                        x1 = f2fma(C3P(base + 7 + m),  t[m], x1);
                        x2 = f2fma(C3P(base + 14 + m), t[m], x2);
                    }
                    bj0 = x0; bj1 = x1; bj2 = x2;
                }
                // symmetric Gram accumulation
                b00 = f2fma(bj0, bj0, b00);
                b01 = f2fma(bj0, bj1, b01);
                b02 = f2fma(bj0, bj2, b02);
                b11 = f2fma(bj1, bj1, b11);
                b12 = f2fma(bj1, bj2, b12);
                b22 = f2fma(bj2, bj2, b22);
                // e[k] += bh[i][j][k] * ah[i][j]
                const pf ahij = ah[i * 3 + j];
                e0 = f2fma(bj0, ahij, e0);
                e1 = f2fma(bj1, ahij, e1);
                e2 = f2fma(bj2, ahij, e2);
                // I8 partial
                pf dj = f2mul(bj0, v[0]);
                dj = f2fma(bj1, v[1], dj);
                dj = f2fma(bj2, v[2], dj);
                i8i = f2fma(v[j], dj, i8i);
            }
            I8 = f2fma(v[i], i8i, I8);
        }
        // t dead now.

        // ---- a = ah^T ah (symmetric) ----
        pf a00 = 0, a01 = 0, a02 = 0, a11 = 0, a12 = 0, a22 = 0;
        #pragma unroll
        for (int i = 0; i < 3; i++) {
            const pf x = ah[i * 3 + 0], y = ah[i * 3 + 1], z = ah[i * 3 + 2];
            a00 = f2fma(x, x, a00); a01 = f2fma(x, y, a01); a02 = f2fma(x, z, a02);
            a11 = f2fma(y, y, a11); a12 = f2fma(y, z, a12); a22 = f2fma(z, z, a22);
        }

        // ---- invariants (packed) ----
        pf I1 = f2mul(v[0], v[0]);
        I1 = f2fma(v[1], v[1], I1);
        I1 = f2fma(v[2], v[2], I1);
        const pf I2 = f2add(f2add(a00, a11), a22);
        const pf I4 = f2add(f2add(b00, b11), b22);

        const pf sum13 = f2add(ah[1], ah[3]);
        const pf sum26 = f2add(ah[2], ah[6]);
        const pf sum57 = f2add(ah[5], ah[7]);

        pf I3 = f2mul(a00, ah[0]);
        I3 = f2fma(a11, ah[4], I3);
        I3 = f2fma(a22, ah[8], I3);
        I3 = f2fma(a01, sum13, I3);
        I3 = f2fma(a02, sum26, I3);
        I3 = f2fma(a12, sum57, I3);

        pf I10 = f2mul(b00, ah[0]);
        I10 = f2fma(b11, ah[4], I10);
        I10 = f2fma(b22, ah[8], I10);
        I10 = f2fma(b01, sum13, I10);
        I10 = f2fma(b02, sum26, I10);
        I10 = f2fma(b12, sum57, I10);

        pf w = f2mul(a01, b01);
        w = f2fma(a02, b02, w);
        w = f2fma(a12, b12, w);
        pf I11 = f2mul(a00, b00);
        I11 = f2fma(a11, b11, I11);
        I11 = f2fma(a22, b22, I11);
        I11 = f2add(I11, f2add(w, w));

        pf w5 = f2mul(b01, b01);
        w5 = f2fma(b02, b02, w5);
        w5 = f2fma(b12, b12, w5);
        pf I5 = f2mul(b00, b00);
        I5 = f2fma(b11, b11, I5);
        I5 = f2fma(b22, b22, I5);
        I5 = f2add(I5, f2add(w5, w5));

        const pf v01 = f2mul(v[0], v[1]);
        const pf v02 = f2mul(v[0], v[2]);
        const pf v12 = f2mul(v[1], v[2]);
        pf w9 = f2mul(v01, b01);
        w9 = f2fma(v02, b02, w9);
        w9 = f2fma(v12, b12, w9);
        pf I9 = f2mul(f2mul(v[0], v[0]), b00);
        I9 = f2fma(f2mul(v[1], v[1]), b11, I9);
        I9 = f2fma(f2mul(v[2], v[2]), b22, I9);
        I9 = f2add(I9, f2add(w9, w9));

        pf cv0 = f2mul(ah[0], v[0]);
        pf cv1 = f2mul(ah[1], v[0]);
        pf cv2 = f2mul(ah[2], v[0]);
        cv0 = f2fma(ah[3], v[1], cv0); cv1 = f2fma(ah[4], v[1], cv1); cv2 = f2fma(ah[5], v[1], cv2);
        cv0 = f2fma(ah[6], v[2], cv0); cv1 = f2fma(ah[7], v[2], cv1); cv2 = f2fma(ah[8], v[2], cv2);
        pf I6 = f2mul(cv0, v[0]);
        I6 = f2fma(cv1, v[1], I6);
        I6 = f2fma(cv2, v[2], I6);
        pf I7 = f2mul(cv0, cv0);
        I7 = f2fma(cv1, cv1, I7);
        I7 = f2fma(cv2, cv2, I7);

        pf I12 = f2mul(e0, e0);
        I12 = f2fma(e1, e1, I12);
        I12 = f2fma(e2, e2, I12);

        // ---- unpack and stage both points into shared ----
        const pf invs[13] = { s, I1, I2, I3, I4, I5, I6, I7, I8, I9, I10, I11, I12 };
        float* soA = &sO[tid * 13];
        float* soB = &sO[(tid + TPB) * 13];
        #pragma unroll
        for (int k = 0; k < 13; k++) {
            float lo, hi;
            f2unpack(invs[k], lo, hi);
            soA[k] = lo;
            soB[k] = hi;
        }
    } else {
        // threads that skip compute still satisfy the PDL dependency cheaply
        cudaGridDependencySynchronize();
    }
    __syncthreads();

    // ---- coalesced writeback ----
    const int valid = min(N - blk_start, PTS_PER_BLK);
    float* obase = out + (size_t)blk_start * 13;

    if (valid == PTS_PER_BLK) {
        const float4* src = reinterpret_cast<const float4*>(sO);
        float4* dst = reinterpret_cast<float4*>(obase);
        #pragma unroll
        for (int i = tid; i < (PTS_PER_BLK * 13) / 4; i += TPB)
            dst[i] = src[i];
    } else {
        const int cnt = valid * 13;
        for (int i = tid; i < cnt; i += TPB)
            obase[i] = sO[i];
    }
#undef C2P
#undef C3P
}

extern "C" void kernel_launch(void* const* d_in, const int* in_sizes, int n_in,
                              void* d_out, int out_size)
{
    const float* tf = (const float*)d_in[0];
    const float* C2 = (const float*)d_in[1];
    const float* C3 = (const float*)d_in[2];
    float* out = (float*)d_out;

    // write packed (c,c) constants straight into cPack's backing store — one
    // kernel node, no memcpy node. Values identical every replay.
    void* csym = nullptr;
    cudaGetSymbolAddress(&csym, cPack);
    prep_kernel<<<1, 256>>>(C2, C3, (unsigned long long*)csym);

    const int N = in_sizes[0] / 16;
    const int blocks = (N + PTS_PER_BLK - 1) / PTS_PER_BLK;

    // PDL: main may launch/overlap while prep finishes; dependency enforced
    // in-kernel via cudaGridDependencySynchronize().
    cudaLaunchConfig_t cfg = {};
    cfg.gridDim = dim3((unsigned)blocks, 1, 1);
    cfg.blockDim = dim3(TPB, 1, 1);
    cfg.dynamicSmemBytes = 0;
    cfg.stream = 0;
    cudaLaunchAttribute attrs[1];
    attrs[0].id = cudaLaunchAttributeProgrammaticStreamSerialization;
    attrs[0].val.programmaticStreamSerializationAllowed = 1;
    cfg.attrs = attrs;
    cfg.numAttrs = 1;
    cudaLaunchKernelEx(&cfg, hop_invariant_kernel, tf, out, N);
}

// round 17
// speedup vs baseline: 1.0391x; 1.0391x over previous
#include <cuda_runtime.h>

#define TPB 64
#define PTS_PER_BLK (2 * TPB)

// one packed (c,c) u64 per coupling constant: [0,45) = C2, [45,234) = C3
// NOTE: must be read as SCALAR u64 (LDCU path); 128-bit reads fall to LDC (8-cyc floor).
__constant__ unsigned long long cPack[234];

// ---------- packed f32x2 helpers ----------
typedef unsigned long long pf;

__device__ __forceinline__ pf f2fma(pf a, pf b, pf c) {
    pf d; asm("fma.rn.f32x2 %0, %1, %2, %3;" : "=l"(d) : "l"(a), "l"(b), "l"(c)); return d;
}
__device__ __forceinline__ pf f2mul(pf a, pf b) {
    pf d; asm("mul.rn.f32x2 %0, %1, %2;" : "=l"(d) : "l"(a), "l"(b)); return d;
}
__device__ __forceinline__ pf f2add(pf a, pf b) {
    pf d; asm("add.rn.f32x2 %0, %1, %2;" : "=l"(d) : "l"(a), "l"(b)); return d;
}
__device__ __forceinline__ pf f2pack(float lo, float hi) {
    pf d; asm("mov.b64 %0, {%1, %2};" : "=l"(d) : "f"(lo), "f"(hi)); return d;
}
__device__ __forceinline__ void f2unpack(pf p, float& lo, float& hi) {
    asm("mov.b64 {%0, %1}, %2;" : "=f"(lo), "=f"(hi) : "l"(p));
}

__global__ void prep_kernel(const float* __restrict__ C2, const float* __restrict__ C3,
                            unsigned long long* __restrict__ dst) {
    int i = threadIdx.x;
    if (i < 234) {
        float c = (i < 45) ? C2[i] : C3[i - 45];
        unsigned int b = __float_as_uint(c);
        dst[i] = ((unsigned long long)b << 32) | b;
    }
}

__global__ __launch_bounds__(TPB, 12)
void hop_invariant_kernel(const float* __restrict__ tf,
                          float* __restrict__ out,
                          int N)
{
    __shared__ __align__(16) float sO[PTS_PER_BLK * 13];

    const unsigned long long* cp = cPack;
#define C2P(i) cp[i]
#define C3P(i) cp[45 + (i)]

    const int tid = threadIdx.x;
    const int blk_start = blockIdx.x * PTS_PER_BLK;
    const int nA = blk_start + tid;
    const int nB = nA + TPB;

    if (nA < N) {
        // ---- load 16 features for both points ----
        float4 a0 = make_float4(0,0,0,0), a1 = a0, a2 = a0, a3 = a0;
        float4 b0 = a0, b1 = a0, b2 = a0, b3 = a0;
        {
            const float4* pA = reinterpret_cast<const float4*>(tf + (size_t)nA * 16);
            a0 = pA[0]; a1 = pA[1]; a2 = pA[2]; a3 = pA[3];
        }
        if (nB < N) {
            const float4* pB = reinterpret_cast<const float4*>(tf + (size_t)nB * 16);
            b0 = pB[0]; b1 = pB[1]; b2 = pB[2]; b3 = pB[3];
        }

        // ---- pack lanes: lo = point A, hi = point B ----
        const pf s  = f2pack(a0.x, b0.x);
        pf v[3] = { f2pack(a0.y, b0.y), f2pack(a0.z, b0.z), f2pack(a0.w, b0.w) };
        pf q[5] = { f2pack(a1.x, b1.x), f2pack(a1.y, b1.y),
                    f2pack(a1.z, b1.z), f2pack(a1.w, b1.w), f2pack(a2.x, b2.x) };
        pf t[7] = { f2pack(a2.y, b2.y), f2pack(a2.z, b2.z), f2pack(a2.w, b2.w),
                    f2pack(a3.x, b3.x), f2pack(a3.y, b3.y), f2pack(a3.z, b3.z),
                    f2pack(a3.w, b3.w) };

        // PDL: wait for prep_kernel's cPack writes before first constant read.
        cudaGridDependencySynchronize();

        // ---- ah[r] = sum_m C2[r][m] * q[m]  (scalar u64 LDCU) ----
        pf ah[9];
        #pragma unroll
        for (int r = 0; r < 9; r++) {
            pf acc = f2mul(C2P(r * 5 + 0), q[0]);
            acc = f2fma(C2P(r * 5 + 1), q[1], acc);
            acc = f2fma(C2P(r * 5 + 2), q[2], acc);
            acc = f2fma(C2P(r * 5 + 3), q[3], acc);
            acc = f2fma(C2P(r * 5 + 4), q[4], acc);
            ah[r] = acc;
        }

        // ---- stream bh 3-at-a-time over (i,j); accumulate b (sym), e, I8 ----
        pf b00 = 0, b01 = 0, b02 = 0, b11 = 0, b12 = 0, b22 = 0;
        pf e0 = 0, e1 = 0, e2 = 0;
        pf I8 = 0;

        #pragma unroll
        for (int i = 0; i < 3; i++) {
            pf i8i = 0;
            #pragma unroll
            for (int j = 0; j < 3; j++) {
                pf bj0, bj1, bj2;
                {
                    const int base = (i * 9 + j * 3) * 7;
                    pf x0 = f2mul(C3P(base + 0), t[0]);
                    pf x1 = f2mul(C3P(base + 7), t[0]);
                    pf x2 = f2mul(C3P(base + 14), t[0]);
                    #pragma unroll
                    for (int m = 1; m < 7; m++) {
                        x0 = f2fma(C3P(base + m),      t[m], x0);
                        x1 = f2fma(C3P(base + 7 + m),  t[m], x1);
                        x2 = f2fma(C3P(base + 14 + m), t[m], x2);
                    }
                    bj0 = x0; bj1 = x1; bj2 = x2;
                }
                // symmetric Gram accumulation
                b00 = f2fma(bj0, bj0, b00);
                b01 = f2fma(bj0, bj1, b01);
                b02 = f2fma(bj0, bj2, b02);
                b11 = f2fma(bj1, bj1, b11);
                b12 = f2fma(bj1, bj2, b12);
                b22 = f2fma(bj2, bj2, b22);
                // e[k] += bh[i][j][k] * ah[i][j]
                const pf ahij = ah[i * 3 + j];
                e0 = f2fma(bj0, ahij, e0);
                e1 = f2fma(bj1, ahij, e1);
                e2 = f2fma(bj2, ahij, e2);
                // I8 partial
                pf dj = f2mul(bj0, v[0]);
                dj = f2fma(bj1, v[1], dj);
                dj = f2fma(bj2, v[2], dj);
                i8i = f2fma(v[j], dj, i8i);
            }
            I8 = f2fma(v[i], i8i, I8);
        }
        // t dead now.

        // ---- a = ah^T ah (symmetric) ----
        pf a00 = 0, a01 = 0, a02 = 0, a11 = 0, a12 = 0, a22 = 0;
        #pragma unroll
        for (int i = 0; i < 3; i++) {
            const pf x = ah[i * 3 + 0], y = ah[i * 3 + 1], z = ah[i * 3 + 2];
            a00 = f2fma(x, x, a00); a01 = f2fma(x, y, a01); a02 = f2fma(x, z, a02);
            a11 = f2fma(y, y, a11); a12 = f2fma(y, z, a12); a22 = f2fma(z, z, a22);
        }

        // ---- invariants (packed) ----
        pf I1 = f2mul(v[0], v[0]);
        I1 = f2fma(v[1], v[1], I1);
        I1 = f2fma(v[2], v[2], I1);
        const pf I2 = f2add(f2add(a00, a11), a22);
        const pf I4 = f2add(f2add(b00, b11), b22);

        const pf sum13 = f2add(ah[1], ah[3]);
        const pf sum26 = f2add(ah[2], ah[6]);
        const pf sum57 = f2add(ah[5], ah[7]);

        pf I3 = f2mul(a00, ah[0]);
        I3 = f2fma(a11, ah[4], I3);
        I3 = f2fma(a22, ah[8], I3);
        I3 = f2fma(a01, sum13, I3);
        I3 = f2fma(a02, sum26, I3);
        I3 = f2fma(a12, sum57, I3);

        pf I10 = f2mul(b00, ah[0]);
        I10 = f2fma(b11, ah[4], I10);
        I10 = f2fma(b22, ah[8], I10);
        I10 = f2fma(b01, sum13, I10);
        I10 = f2fma(b02, sum26, I10);
        I10 = f2fma(b12, sum57, I10);

        pf w = f2mul(a01, b01);
        w = f2fma(a02, b02, w);
        w = f2fma(a12, b12, w);
        pf I11 = f2mul(a00, b00);
        I11 = f2fma(a11, b11, I11);
        I11 = f2fma(a22, b22, I11);
        I11 = f2add(I11, f2add(w, w));

        pf w5 = f2mul(b01, b01);
        w5 = f2fma(b02, b02, w5);
        w5 = f2fma(b12, b12, w5);
        pf I5 = f2mul(b00, b00);
        I5 = f2fma(b11, b11, I5);
        I5 = f2fma(b22, b22, I5);
        I5 = f2add(I5, f2add(w5, w5));

        const pf v01 = f2mul(v[0], v[1]);
        const pf v02 = f2mul(v[0], v[2]);
        const pf v12 = f2mul(v[1], v[2]);
        pf w9 = f2mul(v01, b01);
        w9 = f2fma(v02, b02, w9);
        w9 = f2fma(v12, b12, w9);
        pf I9 = f2mul(f2mul(v[0], v[0]), b00);
        I9 = f2fma(f2mul(v[1], v[1]), b11, I9);
        I9 = f2fma(f2mul(v[2], v[2]), b22, I9);
        I9 = f2add(I9, f2add(w9, w9));

        pf cv0 = f2mul(ah[0], v[0]);
        pf cv1 = f2mul(ah[1], v[0]);
        pf cv2 = f2mul(ah[2], v[0]);
        cv0 = f2fma(ah[3], v[1], cv0); cv1 = f2fma(ah[4], v[1], cv1); cv2 = f2fma(ah[5], v[1], cv2);
        cv0 = f2fma(ah[6], v[2], cv0); cv1 = f2fma(ah[7], v[2], cv1); cv2 = f2fma(ah[8], v[2], cv2);
        pf I6 = f2mul(cv0, v[0]);
        I6 = f2fma(cv1, v[1], I6);
        I6 = f2fma(cv2, v[2], I6);
        pf I7 = f2mul(cv0, cv0);
        I7 = f2fma(cv1, cv1, I7);
        I7 = f2fma(cv2, cv2, I7);

        pf I12 = f2mul(e0, e0);
        I12 = f2fma(e1, e1, I12);
        I12 = f2fma(e2, e2, I12);

        // ---- unpack and stage both points into shared ----
        const pf invs[13] = { s, I1, I2, I3, I4, I5, I6, I7, I8, I9, I10, I11, I12 };
        float* soA = &sO[tid * 13];
        float* soB = &sO[(tid + TPB) * 13];
        #pragma unroll
        for (int k = 0; k < 13; k++) {
            float lo, hi;
            f2unpack(invs[k], lo, hi);
            soA[k] = lo;
            soB[k] = hi;
        }
    } else {
        // threads that skip compute still satisfy the PDL dependency cheaply
        cudaGridDependencySynchronize();
    }
    __syncthreads();

    // ---- coalesced writeback ----
    const int valid = min(N - blk_start, PTS_PER_BLK);
    float* obase = out + (size_t)blk_start * 13;

    if (valid == PTS_PER_BLK) {
        // PTS_PER_BLK*13 floats = 128*13 = 1664 = 416 float4
        const float4* src = reinterpret_cast<const float4*>(sO);
        float4* dst = reinterpret_cast<float4*>(obase);
        #pragma unroll
        for (int i = tid; i < (PTS_PER_BLK * 13) / 4; i += TPB)
            dst[i] = src[i];
    } else {
        const int cnt = valid * 13;
        for (int i = tid; i < cnt; i += TPB)
            obase[i] = sO[i];
    }
#undef C2P
#undef C3P
}

extern "C" void kernel_launch(void* const* d_in, const int* in_sizes, int n_in,
                              void* d_out, int out_size)
{
    const float* tf = (const float*)d_in[0];
    const float* C2 = (const float*)d_in[1];
    const float* C3 = (const float*)d_in[2];
    float* out = (float*)d_out;

    // write packed (c,c) constants straight into cPack's backing store — one
    // kernel node, no memcpy node. Values identical every replay.
    void* csym = nullptr;
    cudaGetSymbolAddress(&csym, cPack);
    prep_kernel<<<1, 256>>>(C2, C3, (unsigned long long*)csym);

    const int N = in_sizes[0] / 16;
    const int blocks = (N + PTS_PER_BLK - 1) / PTS_PER_BLK;

    // PDL: main may launch/overlap while prep finishes; dependency enforced
    // in-kernel via cudaGridDependencySynchronize().
    cudaLaunchConfig_t cfg = {};
    cfg.gridDim = dim3((unsigned)blocks, 1, 1);
    cfg.blockDim = dim3(TPB, 1, 1);
    cfg.dynamicSmemBytes = 0;
    cfg.stream = 0;
    cudaLaunchAttribute attrs[1];
    attrs[0].id = cudaLaunchAttributeProgrammaticStreamSerialization;
    attrs[0].val.programmaticStreamSerializationAllowed = 1;
    cfg.attrs = attrs;
    cfg.numAttrs = 1;
    cudaLaunchKernelEx(&cfg, hop_invariant_kernel, tf, out, N);
}